// round 4
// baseline (speedup 1.0000x reference)
#include <cuda_runtime.h>

#define BH     32
#define LSEQ   4096
#define D      128
#define C      32
#define NCHUNK 128
#define NSPLIT 4

// Scratch (device globals are the allowed scratch mechanism)
__device__ __align__(16) float g_qn[(size_t)BH * LSEQ * D];
__device__ __align__(16) float g_kn[(size_t)BH * LSEQ * D];
__device__ __align__(16) float g_u [(size_t)BH * LSEQ * D];
__device__ __align__(16) float g_w [(size_t)BH * LSEQ * D];
__device__ __align__(16) float g_attn[(size_t)BH * NCHUNK * C * C];

// ---------------------------------------------------------------------------
// Kernel 1: l2-normalize q and k rows. One warp per row (handles q & k rows).
// ---------------------------------------------------------------------------
__global__ void norm_kernel(const float* __restrict__ q,
                            const float* __restrict__ k) {
    int warp = threadIdx.x >> 5;
    int lane = threadIdx.x & 31;
    size_t row = (size_t)blockIdx.x * 8 + warp;   // 0 .. BH*LSEQ-1

    {
        float4 a = ((const float4*)q)[row * 32 + lane];
        float ss = a.x * a.x + a.y * a.y + a.z * a.z + a.w * a.w;
        #pragma unroll
        for (int o = 16; o; o >>= 1) ss += __shfl_xor_sync(0xffffffffu, ss, o);
        float r = rsqrtf(ss + 1e-6f);
        float4 o4 = make_float4(a.x * r, a.y * r, a.z * r, a.w * r);
        ((float4*)g_qn)[row * 32 + lane] = o4;
    }
    {
        float4 a = ((const float4*)k)[row * 32 + lane];
        float ss = a.x * a.x + a.y * a.y + a.z * a.z + a.w * a.w;
        #pragma unroll
        for (int o = 16; o; o >>= 1) ss += __shfl_xor_sync(0xffffffffu, ss, o);
        float r = rsqrtf(ss + 1e-6f);
        float4 o4 = make_float4(a.x * r, a.y * r, a.z * r, a.w * r);
        ((float4*)g_kn)[row * 32 + lane] = o4;
    }
}

// ---------------------------------------------------------------------------
// Kernel 2: per chunk (4096 blocks, 128 threads):
//   A = -(k_beta @ kn^T) * strict_lower; forward substitution; then
//   u = (A+I) @ (beta*v), w = (A+I) @ (beta*kn), attn = (qn @ kn^T)*tril
// ---------------------------------------------------------------------------
__global__ void chunk_kernel(const float* __restrict__ v,
                             const float* __restrict__ beta) {
    __shared__ float knT[128 * 33];     // transposed kn tile, pad 33 (conflict-free cols)
    __shared__ float qn_s[32 * 128];
    __shared__ float A[32 * 33];
    __shared__ float beta_s[32];

    int tid = threadIdx.x;              // 128 threads
    size_t cid = blockIdx.x;            // bh*128 + chunk
    size_t base = cid * 32;             // row base = bh*LSEQ + chunk*32

    for (int idx = tid; idx < 4096; idx += 128) {
        int r = idx >> 7, d = idx & 127;
        knT[d * 33 + r] = g_kn[(base + r) * 128 + d];
        qn_s[idx] = g_qn[base * 128 + idx];
    }
    if (tid < 32) beta_s[tid] = beta[base + tid];
    __syncthreads();

    int j = tid & 31, iw = tid >> 5;    // iw in 0..3, rows i = iw*8+ii

    // A = -(beta_i * kn_i . kn_j), strictly lower
    {
        float acc[8] = {0, 0, 0, 0, 0, 0, 0, 0};
        for (int d = 0; d < 128; d++) {
            float kj = knT[d * 33 + j];
            #pragma unroll
            for (int ii = 0; ii < 8; ii++)
                acc[ii] += knT[d * 33 + (iw * 8 + ii)] * kj;
        }
        #pragma unroll
        for (int ii = 0; ii < 8; ii++) {
            int i = iw * 8 + ii;
            A[i * 33 + j] = (i > j) ? (-beta_s[i] * acc[ii]) : 0.0f;
        }
    }
    __syncthreads();

    // Forward substitution (warp 0): A[i, :i] += A[i, :] @ A[:, :i], i ascending
    if (tid < 32) {
        for (int i = 1; i < 32; i++) {
            float upd = 0.0f;
            for (int t = tid + 1; t < i; t++)
                upd += A[i * 33 + t] * A[t * 33 + tid];
            __syncwarp();
            if (tid < i) A[i * 33 + tid] += upd;
            __syncwarp();
        }
    }
    __syncthreads();

    // attn = (qn @ kn^T) with lower-inclusive mask
    {
        float acc[8] = {0, 0, 0, 0, 0, 0, 0, 0};
        for (int d = 0; d < 128; d++) {
            float kj = knT[d * 33 + j];
            #pragma unroll
            for (int ii = 0; ii < 8; ii++)
                acc[ii] += qn_s[(iw * 8 + ii) * 128 + d] * kj;
        }
        float* ga = g_attn + cid * 1024;
        #pragma unroll
        for (int ii = 0; ii < 8; ii++) {
            int i = iw * 8 + ii;
            ga[i * 32 + j] = (i >= j) ? acc[ii] : 0.0f;
        }
    }

    // u = (A+I) @ (beta*v),  w = (A+I) @ (beta*kn)
    {
        int d32 = tid & 31;              // 4 dv cols: d32*4 .. d32*4+3
        int cw  = tid >> 5;              // 8 rows: cw*8 .. cw*8+7
        float4 au[8], aw[8];
        #pragma unroll
        for (int ii = 0; ii < 8; ii++) {
            int c = cw * 8 + ii;
            float4 vv = *(const float4*)&v[(base + c) * 128 + d32 * 4];
            float4 kk = *(const float4*)&g_kn[(base + c) * 128 + d32 * 4];
            float bc = beta_s[c];
            au[ii] = make_float4(vv.x * bc, vv.y * bc, vv.z * bc, vv.w * bc);
            aw[ii] = make_float4(kk.x * bc, kk.y * bc, kk.z * bc, kk.w * bc);
        }
        for (int t = 0; t < 32; t++) {
            float bt = beta_s[t];
            float4 vv = *(const float4*)&v[(base + t) * 128 + d32 * 4];
            float4 kk = *(const float4*)&g_kn[(base + t) * 128 + d32 * 4];
            vv.x *= bt; vv.y *= bt; vv.z *= bt; vv.w *= bt;
            kk.x *= bt; kk.y *= bt; kk.z *= bt; kk.w *= bt;
            #pragma unroll
            for (int ii = 0; ii < 8; ii++) {
                float a = A[(cw * 8 + ii) * 33 + t];
                au[ii].x += a * vv.x; au[ii].y += a * vv.y;
                au[ii].z += a * vv.z; au[ii].w += a * vv.w;
                aw[ii].x += a * kk.x; aw[ii].y += a * kk.y;
                aw[ii].z += a * kk.z; aw[ii].w += a * kk.w;
            }
        }
        #pragma unroll
        for (int ii = 0; ii < 8; ii++) {
            int c = cw * 8 + ii;
            *(float4*)&g_u[(base + c) * 128 + d32 * 4] = au[ii];
            *(float4*)&g_w[(base + c) * 128 + d32 * 4] = aw[ii];
        }
    }
}

// ---------------------------------------------------------------------------
// Kernel 3: sequential scan over chunks. grid (NSPLIT, BH), 256 threads.
// Each block carries S[128, 32] (its dv slice) in smem.
// ---------------------------------------------------------------------------
__global__ void scan_kernel(float* __restrict__ out) {
    extern __shared__ float sm[];
    float* S  = sm;                // 128*32
    float* qs = sm + 4096;         // 32*128
    float* ks = sm + 8192;         // 32*128
    float* ws = sm + 12288;        // 32*128
    float* us = sm + 16384;        // 32*32
    float* as = sm + 17408;        // 32*32

    int tid = threadIdx.x;
    int bh = blockIdx.y;
    int dvoff = blockIdx.x * 32;
    int j = tid & 31;              // dv column within slice
    int cg = tid >> 5;             // warp id: rows c = cg*4 .. cg*4+3

    for (int i = tid; i < 4096; i += 256) S[i] = 0.0f;

    const float4* gq4 = (const float4*)(g_qn + (size_t)bh * LSEQ * D);
    const float4* gk4 = (const float4*)(g_kn + (size_t)bh * LSEQ * D);
    const float4* gw4 = (const float4*)(g_w  + (size_t)bh * LSEQ * D);
    const float*  ga  = g_attn + (size_t)bh * NCHUNK * 1024;
    const float*  gu  = g_u + (size_t)bh * LSEQ * D;
    float* gout = out + (size_t)bh * LSEQ * D + dvoff;
    __syncthreads();

    for (int ch = 0; ch < NCHUNK; ch++) {
        size_t off4 = (size_t)ch * 1024;
        for (int i = tid; i < 1024; i += 256) {
            ((float4*)qs)[i] = gq4[off4 + i];
            ((float4*)ks)[i] = gk4[off4 + i];
            ((float4*)ws)[i] = gw4[off4 + i];
            as[i] = ga[off4 + i];
        }
        __syncthreads();

        // ---- step 1: u_i = u0 - w_i @ S   (32 x 32)
        float acc[4];
        #pragma unroll
        for (int cc = 0; cc < 4; cc++)
            acc[cc] = gu[(size_t)(ch * 32 + cg * 4 + cc) * 128 + dvoff + j];
        for (int d4 = 0; d4 < 32; d4++) {
            float s0 = S[(d4 * 4 + 0) * 32 + j];
            float s1 = S[(d4 * 4 + 1) * 32 + j];
            float s2 = S[(d4 * 4 + 2) * 32 + j];
            float s3 = S[(d4 * 4 + 3) * 32 + j];
            #pragma unroll
            for (int cc = 0; cc < 4; cc++) {
                float4 w4 = ((const float4*)ws)[(cg * 4 + cc) * 32 + d4];
                acc[cc] -= w4.x * s0 + w4.y * s1 + w4.z * s2 + w4.w * s3;
            }
        }
        #pragma unroll
        for (int cc = 0; cc < 4; cc++)
            us[(cg * 4 + cc) * 32 + j] = acc[cc];
        __syncthreads();

        // ---- step 2: out = q_i @ S + attn @ u_i
        float o[4] = {0, 0, 0, 0};
        for (int d4 = 0; d4 < 32; d4++) {
            float s0 = S[(d4 * 4 + 0) * 32 + j];
            float s1 = S[(d4 * 4 + 1) * 32 + j];
            float s2 = S[(d4 * 4 + 2) * 32 + j];
            float s3 = S[(d4 * 4 + 3) * 32 + j];
            #pragma unroll
            for (int cc = 0; cc < 4; cc++) {
                float4 q4 = ((const float4*)qs)[(cg * 4 + cc) * 32 + d4];
                o[cc] += q4.x * s0 + q4.y * s1 + q4.z * s2 + q4.w * s3;
            }
        }
        for (int t4 = 0; t4 < 8; t4++) {
            float u0 = us[(t4 * 4 + 0) * 32 + j];
            float u1 = us[(t4 * 4 + 1) * 32 + j];
            float u2 = us[(t4 * 4 + 2) * 32 + j];
            float u3 = us[(t4 * 4 + 3) * 32 + j];
            #pragma unroll
            for (int cc = 0; cc < 4; cc++) {
                float4 a4 = ((const float4*)as)[(cg * 4 + cc) * 8 + t4];
                o[cc] += a4.x * u0 + a4.y * u1 + a4.z * u2 + a4.w * u3;
            }
        }
        #pragma unroll
        for (int cc = 0; cc < 4; cc++)
            gout[(size_t)(ch * 32 + cg * 4 + cc) * 128 + j] = o[cc];
        __syncthreads();   // step 2 reads S; step 3 writes S

        // ---- step 3: S += k_i^T @ u_i   (each thread owns 16 S elements)
        int dbase = cg * 16;
        float sacc[16];
        #pragma unroll
        for (int dd = 0; dd < 16; dd++)
            sacc[dd] = S[(dbase + dd) * 32 + j];
        for (int c = 0; c < 32; c++) {
            float uv = us[c * 32 + j];
            #pragma unroll
            for (int dq = 0; dq < 4; dq++) {
                float4 k4 = ((const float4*)ks)[c * 32 + (dbase >> 2) + dq];
                sacc[dq * 4 + 0] += k4.x * uv;
                sacc[dq * 4 + 1] += k4.y * uv;
                sacc[dq * 4 + 2] += k4.z * uv;
                sacc[dq * 4 + 3] += k4.w * uv;
            }
        }
        #pragma unroll
        for (int dd = 0; dd < 16; dd++)
            S[(dbase + dd) * 32 + j] = sacc[dd];
        __syncthreads();
    }
}

// ---------------------------------------------------------------------------
extern "C" void kernel_launch(void* const* d_in, const int* in_sizes, int n_in,
                              void* d_out, int out_size) {
    const float* q    = (const float*)d_in[0];
    const float* k    = (const float*)d_in[1];
    const float* v    = (const float*)d_in[2];
    const float* beta = (const float*)d_in[3];
    float* out = (float*)d_out;

    norm_kernel<<<BH * LSEQ / 8, 256>>>(q, k);
    chunk_kernel<<<BH * NCHUNK, 128>>>(v, beta);

    const int smem_bytes = 18432 * sizeof(float);  // 72 KB
    cudaFuncSetAttribute(scan_kernel,
                         cudaFuncAttributeMaxDynamicSharedMemorySize, smem_bytes);
    scan_kernel<<<dim3(NSPLIT, BH), 256, smem_bytes>>>(out);
}

// round 7
// speedup vs baseline: 1.4315x; 1.4315x over previous
#include <cuda_runtime.h>

#define BH     32
#define LSEQ   4096
#define D      128
#define C      32
#define NCHUNK 128
#define NSPLIT 4

// Scratch (device globals are the allowed scratch mechanism)
__device__ __align__(16) float g_qn[(size_t)BH * LSEQ * D];
__device__ __align__(16) float g_kn[(size_t)BH * LSEQ * D];
__device__ __align__(16) float g_u [(size_t)BH * LSEQ * D];
__device__ __align__(16) float g_w [(size_t)BH * LSEQ * D];
__device__ __align__(16) float g_attn[(size_t)BH * NCHUNK * C * C];

// ---------------------------------------------------------------------------
// Kernel 1: l2-normalize q and k rows. One warp per row (handles q & k rows).
// ---------------------------------------------------------------------------
__global__ void norm_kernel(const float* __restrict__ q,
                            const float* __restrict__ k) {
    int warp = threadIdx.x >> 5;
    int lane = threadIdx.x & 31;
    size_t row = (size_t)blockIdx.x * 8 + warp;   // 0 .. BH*LSEQ-1

    {
        float4 a = ((const float4*)q)[row * 32 + lane];
        float ss = a.x * a.x + a.y * a.y + a.z * a.z + a.w * a.w;
        #pragma unroll
        for (int o = 16; o; o >>= 1) ss += __shfl_xor_sync(0xffffffffu, ss, o);
        float r = rsqrtf(ss + 1e-6f);
        float4 o4 = make_float4(a.x * r, a.y * r, a.z * r, a.w * r);
        ((float4*)g_qn)[row * 32 + lane] = o4;
    }
    {
        float4 a = ((const float4*)k)[row * 32 + lane];
        float ss = a.x * a.x + a.y * a.y + a.z * a.z + a.w * a.w;
        #pragma unroll
        for (int o = 16; o; o >>= 1) ss += __shfl_xor_sync(0xffffffffu, ss, o);
        float r = rsqrtf(ss + 1e-6f);
        float4 o4 = make_float4(a.x * r, a.y * r, a.z * r, a.w * r);
        ((float4*)g_kn)[row * 32 + lane] = o4;
    }
}

// ---------------------------------------------------------------------------
// Kernel 2: per chunk (4096 blocks, 128 threads):
//   A = -(k_beta @ kn^T) * strict_lower; forward substitution; then
//   u = (A+I) @ (beta*v), w = (A+I) @ (beta*kn), attn = (qn @ kn^T)*tril
// ---------------------------------------------------------------------------
__global__ void chunk_kernel(const float* __restrict__ v,
                             const float* __restrict__ beta) {
    __shared__ float knT[128 * 33];     // transposed kn tile, pad 33
    __shared__ float qn_s[32 * 128];
    __shared__ float A[32 * 33];
    __shared__ float beta_s[32];

    int tid = threadIdx.x;              // 128 threads
    size_t cid = blockIdx.x;            // bh*128 + chunk
    size_t base = cid * 32;             // row base = bh*LSEQ + chunk*32

    for (int idx = tid; idx < 4096; idx += 128) {
        int r = idx >> 7, d = idx & 127;
        knT[d * 33 + r] = g_kn[(base + r) * 128 + d];
        qn_s[idx] = g_qn[base * 128 + idx];
    }
    if (tid < 32) beta_s[tid] = beta[base + tid];
    __syncthreads();

    int j = tid & 31, iw = tid >> 5;    // iw in 0..3, rows i = iw*8+ii

    // A = -(beta_i * kn_i . kn_j), strictly lower
    {
        float acc[8] = {0, 0, 0, 0, 0, 0, 0, 0};
        for (int d = 0; d < 128; d++) {
            float kj = knT[d * 33 + j];
            #pragma unroll
            for (int ii = 0; ii < 8; ii++)
                acc[ii] += knT[d * 33 + (iw * 8 + ii)] * kj;
        }
        #pragma unroll
        for (int ii = 0; ii < 8; ii++) {
            int i = iw * 8 + ii;
            A[i * 33 + j] = (i > j) ? (-beta_s[i] * acc[ii]) : 0.0f;
        }
    }
    __syncthreads();

    // Forward substitution (warp 0): A[i, :i] += A[i, :] @ A[:, :i]
    if (tid < 32) {
        for (int i = 1; i < 32; i++) {
            float upd = 0.0f;
            for (int t = tid + 1; t < i; t++)
                upd += A[i * 33 + t] * A[t * 33 + tid];
            __syncwarp();
            if (tid < i) A[i * 33 + tid] += upd;
            __syncwarp();
        }
    }
    __syncthreads();

    // attn = (qn @ kn^T) with lower-inclusive mask
    {
        float acc[8] = {0, 0, 0, 0, 0, 0, 0, 0};
        for (int d = 0; d < 128; d++) {
            float kj = knT[d * 33 + j];
            #pragma unroll
            for (int ii = 0; ii < 8; ii++)
                acc[ii] += qn_s[(iw * 8 + ii) * 128 + d] * kj;
        }
        float* ga = g_attn + cid * 1024;
        #pragma unroll
        for (int ii = 0; ii < 8; ii++) {
            int i = iw * 8 + ii;
            ga[i * 32 + j] = (i >= j) ? acc[ii] : 0.0f;
        }
    }

    // u = (A+I) @ (beta*v),  w = (A+I) @ (beta*kn)
    {
        int d32 = tid & 31;              // 4 cols: d32*4 .. d32*4+3
        int cw  = tid >> 5;              // 8 rows: cw*8 .. cw*8+7
        float4 au[8], aw[8];
        #pragma unroll
        for (int ii = 0; ii < 8; ii++) {
            int c = cw * 8 + ii;
            float4 vv = *(const float4*)&v[(base + c) * 128 + d32 * 4];
            float4 kk = *(const float4*)&g_kn[(base + c) * 128 + d32 * 4];
            float bc = beta_s[c];
            au[ii] = make_float4(vv.x * bc, vv.y * bc, vv.z * bc, vv.w * bc);
            aw[ii] = make_float4(kk.x * bc, kk.y * bc, kk.z * bc, kk.w * bc);
        }
        for (int t = 0; t < 32; t++) {
            float bt = beta_s[t];
            float4 vv = *(const float4*)&v[(base + t) * 128 + d32 * 4];
            float4 kk = *(const float4*)&g_kn[(base + t) * 128 + d32 * 4];
            vv.x *= bt; vv.y *= bt; vv.z *= bt; vv.w *= bt;
            kk.x *= bt; kk.y *= bt; kk.z *= bt; kk.w *= bt;
            #pragma unroll
            for (int ii = 0; ii < 8; ii++) {
                float a = A[(cw * 8 + ii) * 33 + t];
                au[ii].x += a * vv.x; au[ii].y += a * vv.y;
                au[ii].z += a * vv.z; au[ii].w += a * vv.w;
                aw[ii].x += a * kk.x; aw[ii].y += a * kk.y;
                aw[ii].z += a * kk.z; aw[ii].w += a * kk.w;
            }
        }
        #pragma unroll
        for (int ii = 0; ii < 8; ii++) {
            int c = cw * 8 + ii;
            *(float4*)&g_u[(base + c) * 128 + d32 * 4] = au[ii];
            *(float4*)&g_w[(base + c) * 128 + d32 * 4] = aw[ii];
        }
    }
}

// ---------------------------------------------------------------------------
// cp.async helpers
// ---------------------------------------------------------------------------
__device__ __forceinline__ void cpa16(float* s, const void* g) {
    unsigned a = (unsigned)__cvta_generic_to_shared(s);
    asm volatile("cp.async.cg.shared.global [%0], [%1], 16;" :: "r"(a), "l"(g));
}
__device__ __forceinline__ void cpa_commit() {
    asm volatile("cp.async.commit_group;");
}
__device__ __forceinline__ void cpa_wait_all() {
    asm volatile("cp.async.wait_group 0;");
}

// Buffer layout (floats, per buffer):
//   q[4096] @0, k[4096] @4096, w[4096] @8192, attn[1024] @12288, u0[1024] @13312
#define OFF_Q    0
#define OFF_K    4096
#define OFF_W    8192
#define OFF_A    12288
#define OFF_U0   13312
#define BUF_FLOATS 14336

// ---------------------------------------------------------------------------
// Kernel 3: sequential scan over chunks. grid (NSPLIT, BH), 256 threads.
// Double-buffered cp.async prefetch of next chunk's q/k/w/attn/u0-slice.
// Fused (w@S, q@S) d-loop reads the S column once. Two barriers per chunk.
// ---------------------------------------------------------------------------
__global__ void scan_kernel(float* __restrict__ out) {
    extern __shared__ float sm[];
    float* S  = sm;                             // 128*32 = 4096
    float* us = sm + 4096 + 2 * BUF_FLOATS;     // 32*32

    int tid = threadIdx.x;
    int bh = blockIdx.y;
    int dvoff = blockIdx.x * 32;
    int j = tid & 31;              // dv column within slice
    int cg = tid >> 5;             // warp id: rows c = cg*4 .. cg*4+3

    const float4* gq4 = (const float4*)(g_qn + (size_t)bh * LSEQ * D);
    const float4* gk4 = (const float4*)(g_kn + (size_t)bh * LSEQ * D);
    const float4* gw4 = (const float4*)(g_w  + (size_t)bh * LSEQ * D);
    const float4* ga4 = (const float4*)(g_attn + (size_t)bh * NCHUNK * 1024);
    const float*  gu  = g_u + (size_t)bh * LSEQ * D;
    float* gout = out + (size_t)bh * LSEQ * D + dvoff;

    // ---- prefetch chunk 0 into buffer 0
    {
        float* B = sm + 4096;
        for (int i = tid; i < 1024; i += 256) {
            cpa16(B + OFF_Q + 4 * i, gq4 + i);
            cpa16(B + OFF_K + 4 * i, gk4 + i);
            cpa16(B + OFF_W + 4 * i, gw4 + i);
        }
        // attn: 256 float4 = 1024 floats; u0 slice: 32 rows x 32 cols
        cpa16(B + OFF_A + 4 * tid, ga4 + tid);
        {
            int row = tid >> 3, c4 = tid & 7;
            cpa16(B + OFF_U0 + 4 * tid,
                  gu + (size_t)row * 128 + dvoff + c4 * 4);
        }
        cpa_commit();
    }

    for (int i = tid; i < 4096; i += 256) S[i] = 0.0f;

    for (int ch = 0; ch < NCHUNK; ch++) {
        cpa_wait_all();
        __syncthreads();   // current buffer ready; prev chunk's S update done

        float* B = sm + 4096 + (ch & 1) * BUF_FLOATS;
        const float4* qs4 = (const float4*)(B + OFF_Q);
        const float4* ks4 = (const float4*)(B + OFF_K);
        const float4* ws4 = (const float4*)(B + OFF_W);
        const float4* as4 = (const float4*)(B + OFF_A);
        const float*  u0b = B + OFF_U0;

        // ---- prefetch chunk ch+1 into the other buffer (overlaps compute)
        if (ch + 1 < NCHUNK) {
            float* P = sm + 4096 + ((ch + 1) & 1) * BUF_FLOATS;
            size_t off4 = (size_t)(ch + 1) * 1024;
            for (int i = tid; i < 1024; i += 256) {
                cpa16(P + OFF_Q + 4 * i, gq4 + off4 + i);
                cpa16(P + OFF_K + 4 * i, gk4 + off4 + i);
                cpa16(P + OFF_W + 4 * i, gw4 + off4 + i);
            }
            cpa16(P + OFF_A + 4 * tid, ga4 + (size_t)(ch + 1) * 256 + tid);
            {
                int row = tid >> 3, c4 = tid & 7;
                cpa16(P + OFF_U0 + 4 * tid,
                      gu + (size_t)((ch + 1) * 32 + row) * 128 + dvoff + c4 * 4);
            }
            cpa_commit();
        }

        // ---- fused step: u_i = u0 - w_i @ S  and  oq = q_i @ S
        float accU[4], accO[4];
        #pragma unroll
        for (int cc = 0; cc < 4; cc++) {
            accU[cc] = u0b[(cg * 4 + cc) * 32 + j];
            accO[cc] = 0.0f;
        }
        for (int d4 = 0; d4 < 32; d4++) {
            float s0 = S[(d4 * 4 + 0) * 32 + j];
            float s1 = S[(d4 * 4 + 1) * 32 + j];
            float s2 = S[(d4 * 4 + 2) * 32 + j];
            float s3 = S[(d4 * 4 + 3) * 32 + j];
            #pragma unroll
            for (int cc = 0; cc < 4; cc++) {
                float4 w4 = ws4[(cg * 4 + cc) * 32 + d4];
                float4 q4 = qs4[(cg * 4 + cc) * 32 + d4];
                accU[cc] -= w4.x * s0 + w4.y * s1 + w4.z * s2 + w4.w * s3;
                accO[cc] += q4.x * s0 + q4.y * s1 + q4.z * s2 + q4.w * s3;
            }
        }
        #pragma unroll
        for (int cc = 0; cc < 4; cc++)
            us[(cg * 4 + cc) * 32 + j] = accU[cc];
        __syncthreads();   // us ready; all S reads complete

        // ---- out += attn @ u_i ; store
        for (int t4 = 0; t4 < 8; t4++) {
            float u0 = us[(t4 * 4 + 0) * 32 + j];
            float u1 = us[(t4 * 4 + 1) * 32 + j];
            float u2 = us[(t4 * 4 + 2) * 32 + j];
            float u3 = us[(t4 * 4 + 3) * 32 + j];
            #pragma unroll
            for (int cc = 0; cc < 4; cc++) {
                float4 a4 = as4[(cg * 4 + cc) * 8 + t4];
                accO[cc] += a4.x * u0 + a4.y * u1 + a4.z * u2 + a4.w * u3;
            }
        }
        #pragma unroll
        for (int cc = 0; cc < 4; cc++)
            gout[(size_t)(ch * 32 + cg * 4 + cc) * 128 + j] = accO[cc];

        // ---- S += k_i^T @ u_i  (disjoint S rows per warp; no barrier needed:
        //      all S reads finished before the us barrier above)
        int dbase = cg * 16;
        float sacc[16];
        #pragma unroll
        for (int dd = 0; dd < 16; dd++)
            sacc[dd] = S[(dbase + dd) * 32 + j];
        for (int c = 0; c < 32; c++) {
            float uv = us[c * 32 + j];
            #pragma unroll
            for (int dq = 0; dq < 4; dq++) {
                float4 k4 = ks4[c * 32 + (dbase >> 2) + dq];
                sacc[dq * 4 + 0] += k4.x * uv;
                sacc[dq * 4 + 1] += k4.y * uv;
                sacc[dq * 4 + 2] += k4.z * uv;
                sacc[dq * 4 + 3] += k4.w * uv;
            }
        }
        #pragma unroll
        for (int dd = 0; dd < 16; dd++)
            S[(dbase + dd) * 32 + j] = sacc[dd];
        // next iteration's top barrier orders these writes before S reads
    }
}

// ---------------------------------------------------------------------------
extern "C" void kernel_launch(void* const* d_in, const int* in_sizes, int n_in,
                              void* d_out, int out_size) {
    const float* q    = (const float*)d_in[0];
    const float* k    = (const float*)d_in[1];
    const float* v    = (const float*)d_in[2];
    const float* beta = (const float*)d_in[3];
    float* out = (float*)d_out;

    norm_kernel<<<BH * LSEQ / 8, 256>>>(q, k);
    chunk_kernel<<<BH * NCHUNK, 128>>>(v, beta);

    const int smem_bytes = (4096 + 2 * BUF_FLOATS + 1024) * sizeof(float); // 132 KB
    cudaFuncSetAttribute(scan_kernel,
                         cudaFuncAttributeMaxDynamicSharedMemorySize, smem_bytes);
    scan_kernel<<<dim3(NSPLIT, BH), 256, smem_bytes>>>(out);
}